// round 8
// baseline (speedup 1.0000x reference)
#include <cuda_runtime.h>
#include <cstdint>
#include <cstddef>
#include <math.h>

#define B_TOTAL 512
#define T_LEN   256
#define HID     128
#define G4      512
#define WINDOW  8
#define ENCO    128
#define R_ROWS  4
#define NCTA    128
#define NTHR    256
#define K4_SM   26           // k-quads in smem: k 0..103
#define TAIL_Q  6            // k-quads 26..31 (k 104..127) in regs: 12 pairs x 4 cols
#define HROW    72           // padded h row stride in ull (64 data + 8 pad)
#define BT      (B_TOTAL * T_LEN)

typedef unsigned long long ull;

__device__ __forceinline__ ull ffma2(ull a, ull b, ull c) {
    ull d;
    asm("fma.rn.f32x2 %0, %1, %2, %3;" : "=l"(d) : "l"(a), "l"(b), "l"(c));
    return d;
}
__device__ __forceinline__ float lo32(ull v) { return __uint_as_float((unsigned)v); }
__device__ __forceinline__ float hi32(ull v) { return __uint_as_float((unsigned)(v >> 32)); }
__device__ __forceinline__ ull pack2(float a, float b) {
    return (ull)__float_as_uint(a) | ((ull)__float_as_uint(b) << 32);
}
__device__ __forceinline__ float sigf(float x) {
    return __fdividef(1.f, 1.f + __expf(-x));
}
__device__ __forceinline__ float tanhf_(float x) {
    return 1.f - __fdividef(2.f, 1.f + __expf(2.f * x));
}

struct Smem {
    ull   Wq[K4_SM][G4][2];       // 212992 B : W_hh k 0..103
    alignas(16) ull h2[2][R_ROWS][HROW];  // 4608 B : double-buffered h, padded rows
    float tout[R_ROWS][T_LEN];    //   4096 B
    float intv[R_ROWS][T_LEN];    //   4096 B
    float xv[R_ROWS][WINDOW][5];  //    640 B
    float red2[8][R_ROWS];        //    128 B
    float Esm[R_ROWS];            //     16 B
    float stage[640];             //   2560 B
};                                // ~229200 B

// fc1 weights as transposed pairs
__device__ ull g_fc1p[64 * HID];

__global__ void prep_fc1(const float* __restrict__ fc1_w) {
    int idx = blockIdx.x * blockDim.x + threadIdx.x;
    if (idx < 64 * HID) {
        int k2 = idx >> 7, u = idx & 127;
        g_fc1p[idx] = pack2(fc1_w[u * HID + 2 * k2], fc1_w[u * HID + 2 * k2 + 1]);
    }
}

__global__ __launch_bounds__(NTHR, 1)
void modnn_kernel(const float* __restrict__ X,
                  const float* __restrict__ W_ih, const float* __restrict__ W_hh,
                  const float* __restrict__ b_ih, const float* __restrict__ b_hh,
                  const float* __restrict__ fc1_b,
                  const float* __restrict__ fc2_w, const float* __restrict__ fc2_b,
                  const float* __restrict__ int1_w, const float* __restrict__ int1_b,
                  const float* __restrict__ int3_w, const float* __restrict__ int3_b,
                  const float* __restrict__ scale_w, const float* __restrict__ zone_w,
                  float* __restrict__ out)
{
    extern __shared__ char smem_raw[];
    Smem* s = reinterpret_cast<Smem*>(smem_raw);
    const int tid  = threadIdx.x;
    const int b0   = blockIdx.x * R_ROWS;
    const int warp = tid >> 5;
    const int lane = tid & 31;
    const int u    = warp * 16 + (lane >> 1);   // unit 0..127
    const int rg   = lane & 1;                  // my rows: rg and rg+2

    // ---- stage W_hh k=0..103 as [k4][col] 16B quads ----
    for (int idx = tid; idx < K4_SM * G4; idx += NTHR) {
        int k4 = idx >> 9, col = idx & 511;
        const float* wr = W_hh + (size_t)col * HID + 4 * k4;
        s->Wq[k4][col][0] = pack2(wr[0], wr[1]);
        s->Wq[k4][col][1] = pack2(wr[2], wr[3]);
    }
    // int-module staging
    for (int idx = tid; idx < HID * 3; idx += NTHR) s->stage[idx] = int1_w[idx];
    for (int idx = tid; idx < HID; idx += NTHR) {
        s->stage[384 + idx] = int1_b[idx];
        s->stage[512 + idx] = int3_w[idx];
    }

    // ---- per-thread invariants: packed x-weights for my 4 gate cols ----
    ull w01[5], w23[5], bt01, bt23;
    #pragma unroll
    for (int j = 0; j < 5; ++j) {
        w01[j] = pack2(W_ih[(u)       * 5 + j], W_ih[(u + 128) * 5 + j]);
        w23[j] = pack2(W_ih[(u + 256) * 5 + j], W_ih[(u + 384) * 5 + j]);
    }
    bt01 = pack2(b_ih[u]       + b_hh[u],       b_ih[u + 128] + b_hh[u + 128]);
    bt23 = pack2(b_ih[u + 256] + b_hh[u + 256], b_ih[u + 384] + b_hh[u + 384]);

    // ---- W_hh tail (k 104..127 = 12 pairs) for ALL 4 of my gate cols ----
    ull wt[4][2 * TAIL_Q];
    #pragma unroll
    for (int g = 0; g < 4; ++g) {
        const ull* p = reinterpret_cast<const ull*>(W_hh + (size_t)(u + g * 128) * HID + 4 * K4_SM);
        #pragma unroll
        for (int j = 0; j < 2 * TAIL_Q; ++j) wt[g][j] = p[j];
    }
    const float b1r  = fc1_b[u];
    const float w2r  = fc2_w[u];
    const float zone = zone_w[0];
    const float fcb2 = fc2_b[0];
    const float i3b  = int3_b[0];
    const float scl  = scale_w[0];
    __syncthreads();

    // ---- precompute int_all; emit constant outputs; init tout/h/Esm ----
    {
        const float* tmp = s->stage;
        for (int it = tid; it < R_ROWS * T_LEN; it += NTHR) {
            int rr = it >> 8, tt = it & 255;
            const float* Xb = X + (size_t)(b0 + rr) * (T_LEN * 7) + tt * 7;
            float x0 = Xb[3], x1 = Xb[4], x2 = Xb[5];
            float acc = 0.f;
            #pragma unroll 8
            for (int uu2 = 0; uu2 < HID; ++uu2) {
                float v = fmaf(tmp[uu2*3], x0, fmaf(tmp[uu2*3+1], x1, fmaf(tmp[uu2*3+2], x2, tmp[384+uu2])));
                v = fmaxf(v, 0.f);
                acc = fmaf(v, tmp[512 + uu2], acc);
            }
            float val = scl * (1.f / (1.f + expf(-(acc + i3b))));
            s->intv[rr][tt] = val;
            size_t base = (size_t)(b0 + rr) * T_LEN + tt;
            out[(size_t)BT + base]   = Xb[6];                          // HVAC_list
            out[3*(size_t)BT + base] = (tt >= WINDOW) ? val : 0.f;     // Int_list
            if (tt < WINDOW) {
                out[base]                = Xb[0];                      // TOut[:, :w]
                out[2*(size_t)BT + base] = 0.f;                       // Ext zeros
                s->tout[rr][tt] = Xb[0];
            }
        }
        for (int idx = tid; idx < R_ROWS * 64; idx += NTHR)
            s->h2[0][idx >> 6][idx & 63] = pack2(1.f, 1.f);
        if (tid < R_ROWS)
            s->Esm[tid] = X[(size_t)(b0 + tid) * (T_LEN * 7) + WINDOW * 7];
    }
    float cA = 1.f, cB = 1.f;   // cell states for rows rg, rg+2
    __syncthreads();

    // ================= main sequential time loop =================
    for (int i = WINDOW; i < T_LEN; ++i) {
        const bool  enc   = (i < ENCO);
        const float ratio = enc ? (float)i * (1.f / ENCO) : 0.f;

        // ---- window build (32 threads) ----
        if (tid < R_ROWS * WINDOW) {
            int rr = tid >> 3, tt = tid & 7;
            int pos = i - (WINDOW - 1) + tt;
            const float* Xb = X + (size_t)(b0 + rr) * (T_LEN * 7);
            float TO;
            if (tt == WINDOW - 1) {
                TO = s->Esm[rr];
                s->tout[rr][i] = TO;
                out[(size_t)(b0 + rr) * T_LEN + i] = TO;
            } else {
                TO = s->tout[rr][pos];
            }
            float e0 = enc ? fmaf(Xb[pos * 7], ratio, TO * (1.f - ratio)) : TO;
            s->xv[rr][tt][0] = e0;
            #pragma unroll
            for (int j = 1; j < 5; ++j) s->xv[rr][tt][j] = Xb[pos * 7 + j];
        }
        __syncthreads();

        // ---- 8 LSTM sub-steps, ONE barrier each ----
        #pragma unroll 1
        for (int st = 0; st < WINDOW; ++st) {
            const int pb = st & 1;
            const ull* hArow = s->h2[pb][rg];
            const ull* hBrow = s->h2[pb][rg + 2];

            // x-part: packed (i,f)/(g,o) pre-activations for rows rg (A) and rg+2 (B)
            ull fA01 = bt01, fA23 = bt23, fB01 = bt01, fB23 = bt23;
            #pragma unroll
            for (int j = 0; j < 5; ++j) {
                float xa = s->xv[rg][st][j];
                float xb = s->xv[rg + 2][st][j];
                ull xpa = pack2(xa, xa), xpb = pack2(xb, xb);
                fA01 = ffma2(xpa, w01[j], fA01);
                fA23 = ffma2(xpa, w23[j], fA23);
                fB01 = ffma2(xpb, w01[j], fB01);
                fB23 = ffma2(xpb, w23[j], fB23);
            }

            // main dots: 4 gate cols x 2 rows, k 0..103 (smem W)
            ull a0A = 0, a1A = 0, a2A = 0, a3A = 0;
            ull a0B = 0, a1B = 0, a2B = 0, a3B = 0;
            #pragma unroll 2
            for (int k4 = 0; k4 < K4_SM; ++k4) {
                ulonglong2 hA = *reinterpret_cast<const ulonglong2*>(&hArow[2 * k4]);
                ulonglong2 hB = *reinterpret_cast<const ulonglong2*>(&hBrow[2 * k4]);
                ulonglong2 q0 = *reinterpret_cast<const ulonglong2*>(&s->Wq[k4][u][0]);
                ulonglong2 q1 = *reinterpret_cast<const ulonglong2*>(&s->Wq[k4][u + 128][0]);
                ulonglong2 q2 = *reinterpret_cast<const ulonglong2*>(&s->Wq[k4][u + 256][0]);
                ulonglong2 q3 = *reinterpret_cast<const ulonglong2*>(&s->Wq[k4][u + 384][0]);
                a0A = ffma2(q0.x, hA.x, a0A);  a0A = ffma2(q0.y, hA.y, a0A);
                a1A = ffma2(q1.x, hA.x, a1A);  a1A = ffma2(q1.y, hA.y, a1A);
                a2A = ffma2(q2.x, hA.x, a2A);  a2A = ffma2(q2.y, hA.y, a2A);
                a3A = ffma2(q3.x, hA.x, a3A);  a3A = ffma2(q3.y, hA.y, a3A);
                a0B = ffma2(q0.x, hB.x, a0B);  a0B = ffma2(q0.y, hB.y, a0B);
                a1B = ffma2(q1.x, hB.x, a1B);  a1B = ffma2(q1.y, hB.y, a1B);
                a2B = ffma2(q2.x, hB.x, a2B);  a2B = ffma2(q2.y, hB.y, a2B);
                a3B = ffma2(q3.x, hB.x, a3B);  a3B = ffma2(q3.y, hB.y, a3B);
            }
            // register tail: k 104..127, FULLY UNROLLED (static indices)
            #pragma unroll
            for (int q = 0; q < TAIL_Q; ++q) {
                ulonglong2 hA = *reinterpret_cast<const ulonglong2*>(&hArow[2 * (K4_SM + q)]);
                ulonglong2 hB = *reinterpret_cast<const ulonglong2*>(&hBrow[2 * (K4_SM + q)]);
                a0A = ffma2(wt[0][2*q], hA.x, a0A);  a0A = ffma2(wt[0][2*q+1], hA.y, a0A);
                a1A = ffma2(wt[1][2*q], hA.x, a1A);  a1A = ffma2(wt[1][2*q+1], hA.y, a1A);
                a2A = ffma2(wt[2][2*q], hA.x, a2A);  a2A = ffma2(wt[2][2*q+1], hA.y, a2A);
                a3A = ffma2(wt[3][2*q], hA.x, a3A);  a3A = ffma2(wt[3][2*q+1], hA.y, a3A);
                a0B = ffma2(wt[0][2*q], hB.x, a0B);  a0B = ffma2(wt[0][2*q+1], hB.y, a0B);
                a1B = ffma2(wt[1][2*q], hB.x, a1B);  a1B = ffma2(wt[1][2*q+1], hB.y, a1B);
                a2B = ffma2(wt[2][2*q], hB.x, a2B);  a2B = ffma2(wt[2][2*q+1], hB.y, a2B);
                a3B = ffma2(wt[3][2*q], hB.x, a3B);  a3B = ffma2(wt[3][2*q+1], hB.y, a3B);
            }

            // phase 2 (thread-local), rows rg and rg+2 interleaved for MUFU ILP
            float giA = lo32(fA01) + lo32(a0A) + hi32(a0A);
            float gfA = hi32(fA01) + lo32(a1A) + hi32(a1A);
            float ggA = lo32(fA23) + lo32(a2A) + hi32(a2A);
            float goA = hi32(fA23) + lo32(a3A) + hi32(a3A);
            float giB = lo32(fB01) + lo32(a0B) + hi32(a0B);
            float gfB = hi32(fB01) + lo32(a1B) + hi32(a1B);
            float ggB = lo32(fB23) + lo32(a2B) + hi32(a2B);
            float goB = hi32(fB23) + lo32(a3B) + hi32(a3B);

            cA = sigf(gfA) * cA + sigf(giA) * tanhf_(ggA);
            cB = sigf(gfB) * cB + sigf(giB) * tanhf_(ggB);
            float hvA = sigf(goA) * tanhf_(cA);
            float hvB = sigf(goB) * tanhf_(cB);

            float* hf = reinterpret_cast<float*>(&s->h2[pb ^ 1][0][0]);
            hf[(rg)     * (2 * HROW) + u] = hvA;
            hf[(rg + 2) * (2 * HROW) + u] = hvB;
            __syncthreads();
        }

        // ---- ext head: unit u, rows rg / rg+2 (final h in buffer 0) ----
        {
            const ull* hA = s->h2[0][rg];
            const ull* hB = s->h2[0][rg + 2];
            ull A0 = 0, A1 = 0;
            #pragma unroll 8
            for (int k2 = 0; k2 < 64; ++k2) {
                ull w = __ldg(&g_fc1p[k2 * HID + u]);
                A0 = ffma2(w, hA[k2], A0);
                A1 = ffma2(w, hB[k2], A1);
            }
            float p0 = fmaxf(lo32(A0) + hi32(A0) + b1r, 0.f) * w2r;
            float p1 = fmaxf(lo32(A1) + hi32(A1) + b1r, 0.f) * w2r;
            #pragma unroll
            for (int m = 2; m <= 16; m <<= 1) {   // reduce over u slots, keep rg parity
                p0 += __shfl_xor_sync(0xFFFFFFFFu, p0, m);
                p1 += __shfl_xor_sync(0xFFFFFFFFu, p1, m);
            }
            if (lane < 2) {
                s->red2[warp][rg]     = p0;   // row rg
                s->red2[warp][rg + 2] = p1;   // row rg+2
            }
        }
        __syncthreads();

        // ---- scalar tail: ext, total, E update ----
        if (tid < R_ROWS) {
            int rr = tid;
            float dot = 0.f;
            #pragma unroll
            for (int w = 0; w < 8; ++w) dot += s->red2[w][rr];
            float ext = dot + fcb2;
            const float* Xb = X + (size_t)(b0 + rr) * (T_LEN * 7);
            float hv = Xb[i * 7 + 6];
            float it = s->intv[rr][i];
            float total = ext + hv + it;
            out[2*(size_t)BT + (size_t)(b0 + rr) * T_LEN + i] = ext;
            float E = s->Esm[rr];
            if (enc) E = ratio * Xb[i * 7] + (1.f - ratio) * E + total * zone;
            else     E = total * zone + E;
            s->Esm[rr] = E;
        }
        __syncthreads();
    }
}

extern "C" void kernel_launch(void* const* d_in, const int* in_sizes, int n_in,
                              void* d_out, int out_size) {
    const float* X       = (const float*)d_in[0];
    const float* W_ih    = (const float*)d_in[1];
    const float* W_hh    = (const float*)d_in[2];
    const float* b_ih    = (const float*)d_in[3];
    const float* b_hh    = (const float*)d_in[4];
    const float* fc1_w   = (const float*)d_in[5];
    const float* fc1_b   = (const float*)d_in[6];
    const float* fc2_w   = (const float*)d_in[7];
    const float* fc2_b   = (const float*)d_in[8];
    const float* int1_w  = (const float*)d_in[9];
    const float* int1_b  = (const float*)d_in[10];
    const float* int3_w  = (const float*)d_in[11];
    const float* int3_b  = (const float*)d_in[12];
    const float* scale_w = (const float*)d_in[13];
    const float* zone_w  = (const float*)d_in[14];
    float* out = (float*)d_out;

    prep_fc1<<<64, 128>>>(fc1_w);

    size_t smem = sizeof(Smem);
    cudaFuncSetAttribute(modnn_kernel, cudaFuncAttributeMaxDynamicSharedMemorySize, (int)smem);
    modnn_kernel<<<NCTA, NTHR, smem>>>(X, W_ih, W_hh, b_ih, b_hh,
                                       fc1_b, fc2_w, fc2_b,
                                       int1_w, int1_b, int3_w, int3_b,
                                       scale_w, zone_w, out);
}

// round 9
// speedup vs baseline: 1.0258x; 1.0258x over previous
#include <cuda_runtime.h>
#include <cstdint>
#include <cstddef>
#include <math.h>

#define B_TOTAL 512
#define T_LEN   256
#define HID     128
#define G4      512
#define WINDOW  8
#define ENCO    128
#define R_ROWS  4
#define NCTA    128
#define NTHR    512
#define K4_SM   24           // k-quads in smem: k 0..95 (group0: quads 0..11, group1: 12..23)
#define BT      (B_TOTAL * T_LEN)

typedef unsigned long long ull;

__device__ __forceinline__ ull ffma2(ull a, ull b, ull c) {
    ull d;
    asm("fma.rn.f32x2 %0, %1, %2, %3;" : "=l"(d) : "l"(a), "l"(b), "l"(c));
    return d;
}
__device__ __forceinline__ float lo32(ull v) { return __uint_as_float((unsigned)v); }
__device__ __forceinline__ float hi32(ull v) { return __uint_as_float((unsigned)(v >> 32)); }
__device__ __forceinline__ ull pack2(float a, float b) {
    return (ull)__float_as_uint(a) | ((ull)__float_as_uint(b) << 32);
}
__device__ __forceinline__ float sigf(float x) {
    return __fdividef(1.f, 1.f + __expf(-x));
}
__device__ __forceinline__ float tanhf_(float x) {
    return 1.f - __fdividef(2.f, 1.f + __expf(2.f * x));
}

struct Smem {
    ull   Wq[K4_SM][G4][2];        // 196608 B : W_hh k 0..95
    alignas(16) ull h2[R_ROWS][HID/2];   // 2048 B : hidden state (single buffer)
    float gp[2][R_ROWS][G4];       //  16384 B : gate partials per K-half
    float tout[R_ROWS][T_LEN];     //   4096 B
    float intv[R_ROWS][T_LEN];     //   4096 B
    float xv[R_ROWS][WINDOW][5];   //    640 B
    float red[R_ROWS][4];          //     64 B
    float Esm[R_ROWS];             //     16 B
    float stage[640];              //   2560 B (init only)
};                                 // ~226.5 KB

// fc1 weights as transposed pairs
__device__ ull g_fc1p[64 * HID];

__global__ void prep_fc1(const float* __restrict__ fc1_w) {
    int idx = blockIdx.x * blockDim.x + threadIdx.x;
    if (idx < 64 * HID) {
        int k2 = idx >> 7, u = idx & 127;
        g_fc1p[idx] = pack2(fc1_w[u * HID + 2 * k2], fc1_w[u * HID + 2 * k2 + 1]);
    }
}

__global__ __launch_bounds__(NTHR, 1)
void modnn_kernel(const float* __restrict__ X,
                  const float* __restrict__ W_ih, const float* __restrict__ W_hh,
                  const float* __restrict__ b_ih, const float* __restrict__ b_hh,
                  const float* __restrict__ fc1_b,
                  const float* __restrict__ fc2_w, const float* __restrict__ fc2_b,
                  const float* __restrict__ int1_w, const float* __restrict__ int1_b,
                  const float* __restrict__ int3_w, const float* __restrict__ int3_b,
                  const float* __restrict__ scale_w, const float* __restrict__ zone_w,
                  float* __restrict__ out)
{
    extern __shared__ char smem_raw[];
    Smem* s = reinterpret_cast<Smem*>(smem_raw);
    const int tid = threadIdx.x;
    const int b0  = blockIdx.x * R_ROWS;
    const int kh  = tid >> 8;        // K-half group: 0 or 1
    const int c2  = tid & 255;       // my column base (cols c2 and c2+256)
    const int kq0 = kh * 12;         // smem k-quad base (12 quads each)
    const int tp  = 48 + kh * 8;     // register-tail pair base (8 pairs each)

    // ---- stage W_hh k=0..95 as [k4][col] 16B quads ----
    for (int idx = tid; idx < K4_SM * G4; idx += NTHR) {
        int k4 = idx >> 9, col = idx & 511;
        const float* wr = W_hh + (size_t)col * HID + 4 * k4;
        s->Wq[k4][col][0] = pack2(wr[0], wr[1]);
        s->Wq[k4][col][1] = pack2(wr[2], wr[3]);
    }
    // int-module staging
    for (int idx = tid; idx < HID * 3; idx += NTHR) s->stage[idx] = int1_w[idx];
    for (int idx = tid; idx < HID; idx += NTHR) {
        s->stage[384 + idx] = int1_b[idx];
        s->stage[512 + idx] = int3_w[idx];
    }

    // ---- per-thread invariants ----
    // x-part weights (used by kh==0 only, but uniform allocation)
    float wihA[5], wihB[5];
    #pragma unroll
    for (int j = 0; j < 5; ++j) {
        wihA[j] = W_ih[c2 * 5 + j];
        wihB[j] = W_ih[(c2 + 256) * 5 + j];
    }
    const float btA = b_ih[c2] + b_hh[c2];
    const float btB = b_ih[c2 + 256] + b_hh[c2 + 256];

    // register tail: 8 pairs for each of my 2 columns
    ull wtA[8], wtB[8];
    {
        const ull* pA = reinterpret_cast<const ull*>(W_hh + (size_t)c2 * HID) + tp;
        const ull* pB = reinterpret_cast<const ull*>(W_hh + (size_t)(c2 + 256) * HID) + tp;
        #pragma unroll
        for (int j = 0; j < 8; ++j) { wtA[j] = pA[j]; wtB[j] = pB[j]; }
    }

    // phase-2 mapping: thread <-> (row r2, unit u2)
    const int r2 = tid >> 7;
    const int u2 = tid & 127;
    const float b1r  = fc1_b[u2];
    const float w2r  = fc2_w[u2];
    const float zone = zone_w[0];
    const float fcb2 = fc2_b[0];
    const float i3b  = int3_b[0];
    const float scl  = scale_w[0];
    __syncthreads();

    // ---- precompute int_all; emit constant outputs; init tout/h/Esm ----
    {
        const float* tmp = s->stage;
        for (int it = tid; it < R_ROWS * T_LEN; it += NTHR) {
            int rr = it >> 8, tt = it & 255;
            const float* Xb = X + (size_t)(b0 + rr) * (T_LEN * 7) + tt * 7;
            float x0 = Xb[3], x1 = Xb[4], x2 = Xb[5];
            float acc = 0.f;
            #pragma unroll 8
            for (int uu = 0; uu < HID; ++uu) {
                float v = fmaf(tmp[uu*3], x0, fmaf(tmp[uu*3+1], x1, fmaf(tmp[uu*3+2], x2, tmp[384+uu])));
                v = fmaxf(v, 0.f);
                acc = fmaf(v, tmp[512 + uu], acc);
            }
            float val = scl * (1.f / (1.f + expf(-(acc + i3b))));
            s->intv[rr][tt] = val;
            size_t base = (size_t)(b0 + rr) * T_LEN + tt;
            out[(size_t)BT + base]   = Xb[6];                          // HVAC_list
            out[3*(size_t)BT + base] = (tt >= WINDOW) ? val : 0.f;     // Int_list
            if (tt < WINDOW) {
                out[base]                = Xb[0];                      // TOut[:, :w]
                out[2*(size_t)BT + base] = 0.f;                        // Ext zeros
                s->tout[rr][tt] = Xb[0];
            }
        }
        for (int idx = tid; idx < R_ROWS * (HID/2); idx += NTHR)
            s->h2[idx >> 6][idx & 63] = pack2(1.f, 1.f);
        if (tid < R_ROWS)
            s->Esm[tid] = X[(size_t)(b0 + tid) * (T_LEN * 7) + WINDOW * 7];
    }
    float cst = 1.f;   // cell state for (r2, u2)
    __syncthreads();

    // ================= main sequential time loop =================
    for (int i = WINDOW; i < T_LEN; ++i) {
        const bool  enc   = (i < ENCO);
        const float ratio = enc ? (float)i * (1.f / ENCO) : 0.f;

        // ---- window build (32 threads) ----
        if (tid < R_ROWS * WINDOW) {
            int rr = tid >> 3, tt = tid & 7;
            int pos = i - (WINDOW - 1) + tt;
            const float* Xb = X + (size_t)(b0 + rr) * (T_LEN * 7);
            float TO;
            if (tt == WINDOW - 1) {
                TO = s->Esm[rr];
                s->tout[rr][i] = TO;
                out[(size_t)(b0 + rr) * T_LEN + i] = TO;
            } else {
                TO = s->tout[rr][pos];
            }
            float e0 = enc ? fmaf(Xb[pos * 7], ratio, TO * (1.f - ratio)) : TO;
            s->xv[rr][tt][0] = e0;
            #pragma unroll
            for (int j = 1; j < 5; ++j) s->xv[rr][tt][j] = Xb[pos * 7 + j];
        }
        __syncthreads();

        // ---- 8 LSTM sub-steps, 2 barriers each ----
        #pragma unroll 1
        for (int st = 0; st < WINDOW; ++st) {
            // partial dots for cols c2, c2+256, rows 0..3, over my K-half
            float init0[R_ROWS], init1[R_ROWS];
            if (kh == 0) {
                #pragma unroll
                for (int r = 0; r < R_ROWS; ++r) {
                    float v0 = btA, v1 = btB;
                    #pragma unroll
                    for (int j = 0; j < 5; ++j) {
                        float xj = s->xv[r][st][j];
                        v0 = fmaf(xj, wihA[j], v0);
                        v1 = fmaf(xj, wihB[j], v1);
                    }
                    init0[r] = v0; init1[r] = v1;
                }
            } else {
                #pragma unroll
                for (int r = 0; r < R_ROWS; ++r) { init0[r] = 0.f; init1[r] = 0.f; }
            }

            ull a00 = 0, a01 = 0, a02 = 0, a03 = 0;
            ull a10 = 0, a11 = 0, a12 = 0, a13 = 0;
            const ulonglong2* hq0 = reinterpret_cast<const ulonglong2*>(s->h2[0]);
            const ulonglong2* hq1 = reinterpret_cast<const ulonglong2*>(s->h2[1]);
            const ulonglong2* hq2 = reinterpret_cast<const ulonglong2*>(s->h2[2]);
            const ulonglong2* hq3 = reinterpret_cast<const ulonglong2*>(s->h2[3]);

            // smem W: 12 k-quads of my K-half
            #pragma unroll 2
            for (int k4 = kq0; k4 < kq0 + 12; ++k4) {
                ulonglong2 w0 = *reinterpret_cast<const ulonglong2*>(&s->Wq[k4][c2][0]);
                ulonglong2 w1 = *reinterpret_cast<const ulonglong2*>(&s->Wq[k4][c2 + 256][0]);
                ulonglong2 h0 = hq0[k4], h1 = hq1[k4], h2 = hq2[k4], h3 = hq3[k4];
                a00 = ffma2(w0.x, h0.x, a00);  a00 = ffma2(w0.y, h0.y, a00);
                a10 = ffma2(w1.x, h0.x, a10);  a10 = ffma2(w1.y, h0.y, a10);
                a01 = ffma2(w0.x, h1.x, a01);  a01 = ffma2(w0.y, h1.y, a01);
                a11 = ffma2(w1.x, h1.x, a11);  a11 = ffma2(w1.y, h1.y, a11);
                a02 = ffma2(w0.x, h2.x, a02);  a02 = ffma2(w0.y, h2.y, a02);
                a12 = ffma2(w1.x, h2.x, a12);  a12 = ffma2(w1.y, h2.y, a12);
                a03 = ffma2(w0.x, h3.x, a03);  a03 = ffma2(w0.y, h3.y, a03);
                a13 = ffma2(w1.x, h3.x, a13);  a13 = ffma2(w1.y, h3.y, a13);
            }
            // register tail: 8 pairs (4 ulonglong2 of h), FULLY UNROLLED
            #pragma unroll
            for (int j = 0; j < 4; ++j) {
                ulonglong2 h0 = *reinterpret_cast<const ulonglong2*>(&s->h2[0][tp + 2*j]);
                ulonglong2 h1 = *reinterpret_cast<const ulonglong2*>(&s->h2[1][tp + 2*j]);
                ulonglong2 h2 = *reinterpret_cast<const ulonglong2*>(&s->h2[2][tp + 2*j]);
                ulonglong2 h3 = *reinterpret_cast<const ulonglong2*>(&s->h2[3][tp + 2*j]);
                ull wa0 = wtA[2*j], wb0 = wtA[2*j+1];
                ull wa1 = wtB[2*j], wb1 = wtB[2*j+1];
                a00 = ffma2(wa0, h0.x, a00);  a00 = ffma2(wb0, h0.y, a00);
                a10 = ffma2(wa1, h0.x, a10);  a10 = ffma2(wb1, h0.y, a10);
                a01 = ffma2(wa0, h1.x, a01);  a01 = ffma2(wb0, h1.y, a01);
                a11 = ffma2(wa1, h1.x, a11);  a11 = ffma2(wb1, h1.y, a11);
                a02 = ffma2(wa0, h2.x, a02);  a02 = ffma2(wb0, h2.y, a02);
                a12 = ffma2(wa1, h2.x, a12);  a12 = ffma2(wb1, h2.y, a12);
                a03 = ffma2(wa0, h3.x, a03);  a03 = ffma2(wb0, h3.y, a03);
                a13 = ffma2(wa1, h3.x, a13);  a13 = ffma2(wb1, h3.y, a13);
            }
            s->gp[kh][0][c2]       = init0[0] + lo32(a00) + hi32(a00);
            s->gp[kh][1][c2]       = init0[1] + lo32(a01) + hi32(a01);
            s->gp[kh][2][c2]       = init0[2] + lo32(a02) + hi32(a02);
            s->gp[kh][3][c2]       = init0[3] + lo32(a03) + hi32(a03);
            s->gp[kh][0][c2 + 256] = init1[0] + lo32(a10) + hi32(a10);
            s->gp[kh][1][c2 + 256] = init1[1] + lo32(a11) + hi32(a11);
            s->gp[kh][2][c2 + 256] = init1[2] + lo32(a12) + hi32(a12);
            s->gp[kh][3][c2 + 256] = init1[3] + lo32(a13) + hi32(a13);
            __syncthreads();

            // phase 2: thread-local c/h for (r2, u2)
            {
                float gi = s->gp[0][r2][u2]       + s->gp[1][r2][u2];
                float gf = s->gp[0][r2][u2 + 128] + s->gp[1][r2][u2 + 128];
                float gg = s->gp[0][r2][u2 + 256] + s->gp[1][r2][u2 + 256];
                float go = s->gp[0][r2][u2 + 384] + s->gp[1][r2][u2 + 384];
                cst = sigf(gf) * cst + sigf(gi) * tanhf_(gg);
                float hv = sigf(go) * tanhf_(cst);
                reinterpret_cast<float*>(&s->h2[0][0])[r2 * HID + u2] = hv;
            }
            __syncthreads();
        }

        // ---- ext head (first 256 threads, 2 rows each, shared fc1 loads) ----
        if (kh == 0) {
            const int rA = r2;            // 0 or 1 (since tid < 256)
            const ull* hA = s->h2[rA];
            const ull* hB = s->h2[rA + 2];
            ull A0 = 0, A1 = 0;
            #pragma unroll 8
            for (int k2 = 0; k2 < 64; ++k2) {
                ull w = __ldg(&g_fc1p[k2 * HID + u2]);
                A0 = ffma2(w, hA[k2], A0);
                A1 = ffma2(w, hB[k2], A1);
            }
            float p0 = fmaxf(lo32(A0) + hi32(A0) + b1r, 0.f) * w2r;
            float p1 = fmaxf(lo32(A1) + hi32(A1) + b1r, 0.f) * w2r;
            #pragma unroll
            for (int m = 16; m > 0; m >>= 1) {
                p0 += __shfl_xor_sync(0xFFFFFFFFu, p0, m);
                p1 += __shfl_xor_sync(0xFFFFFFFFu, p1, m);
            }
            if ((tid & 31) == 0) {
                int w8 = tid >> 5;                 // 0..7
                s->red[rA][w8 & 3]     = p0;
                s->red[rA + 2][w8 & 3] = p1;
            }
        }
        __syncthreads();

        // ---- scalar tail ----
        if (tid < R_ROWS) {
            int rr = tid;
            float dot = s->red[rr][0] + s->red[rr][1] + s->red[rr][2] + s->red[rr][3];
            float ext = dot + fcb2;
            const float* Xb = X + (size_t)(b0 + rr) * (T_LEN * 7);
            float hv = Xb[i * 7 + 6];
            float it = s->intv[rr][i];
            float total = ext + hv + it;
            out[2*(size_t)BT + (size_t)(b0 + rr) * T_LEN + i] = ext;
            float E = s->Esm[rr];
            if (enc) E = ratio * Xb[i * 7] + (1.f - ratio) * E + total * zone;
            else     E = total * zone + E;
            s->Esm[rr] = E;
        }
        __syncthreads();
    }
}

extern "C" void kernel_launch(void* const* d_in, const int* in_sizes, int n_in,
                              void* d_out, int out_size) {
    const float* X       = (const float*)d_in[0];
    const float* W_ih    = (const float*)d_in[1];
    const float* W_hh    = (const float*)d_in[2];
    const float* b_ih    = (const float*)d_in[3];
    const float* b_hh    = (const float*)d_in[4];
    const float* fc1_w   = (const float*)d_in[5];
    const float* fc1_b   = (const float*)d_in[6];
    const float* fc2_w   = (const float*)d_in[7];
    const float* fc2_b   = (const float*)d_in[8];
    const float* int1_w  = (const float*)d_in[9];
    const float* int1_b  = (const float*)d_in[10];
    const float* int3_w  = (const float*)d_in[11];
    const float* int3_b  = (const float*)d_in[12];
    const float* scale_w = (const float*)d_in[13];
    const float* zone_w  = (const float*)d_in[14];
    float* out = (float*)d_out;

    prep_fc1<<<64, 128>>>(fc1_w);

    size_t smem = sizeof(Smem);
    cudaFuncSetAttribute(modnn_kernel, cudaFuncAttributeMaxDynamicSharedMemorySize, (int)smem);
    modnn_kernel<<<NCTA, NTHR, smem>>>(X, W_ih, W_hh, b_ih, b_hh,
                                       fc1_b, fc2_w, fc2_b,
                                       int1_w, int1_b, int3_w, int3_b,
                                       scale_w, zone_w, out);
}